// round 12
// baseline (speedup 1.0000x reference)
#include <cuda_runtime.h>

// Problem constants: B=32, S1=14, S2=14, NC=2, DC=16, F=32, I=8
#define NROWS   200704      // B*S1*S2*NC*DC
#define DE      32          // NC*DC (weights repeat with row period 32)
#define HALF    51380224    // NROWS * F * I (elements per output tensor)

__device__ __forceinline__ float ex2a(float x) {
    float y; asm("ex2.approx.ftz.f32 %0, %1;" : "=f"(y) : "f"(x)); return y;
}
__device__ __forceinline__ float rcpa(float x) {
    float y; asm("rcp.approx.ftz.f32 %0, %1;" : "=f"(y) : "f"(x)); return y;
}

// R2 body (one warp per row, fully-coalesced 512B LDG.128/STG.128, 32 regs,
// 8 blocks/SM) + a cheap block prologue that computes the exact
// maxWt[de,i] for the block's 8 rows into shared memory — replacing the
// separate prep kernel (which cost ~6us of graph launch overhead).
__global__ void __launch_bounds__(256, 8)
mhsa_main(const float* __restrict__ U,
          const float* __restrict__ Wt,
          const float* __restrict__ Wa,
          float* __restrict__ outC,
          float* __restrict__ outUI)
{
    __shared__ __align__(16) float s_wm[64];   // [warp_in_block][i]

    const int tid = threadIdx.x;

    // ---- prologue: wm[w][i] = max_f Wt[de(w), f, i] for this block's 8 rows.
    // 4 threads per (w,i) pair; each maxes 8 f's (L1-resident scalar loads),
    // then a 2-step intra-quad shuffle-max; part==0 stores to smem.
    {
        const int p    = tid >> 2;          // 0..63 : p = w*8 + i
        const int part = tid & 3;           // f-chunk 0..3
        const int w_l  = p >> 3;
        const int i    = p & 7;
        const int de   = ((blockIdx.x << 3) + w_l) & (DE - 1);
        const float* q = Wt + de * 256 + part * 64 + i;
        float m = q[0];
        #pragma unroll
        for (int k = 1; k < 8; ++k) m = fmaxf(m, q[k * 8]);
        m = fmaxf(m, __shfl_xor_sync(0xffffffffu, m, 1));
        m = fmaxf(m, __shfl_xor_sync(0xffffffffu, m, 2));
        if (part == 0) s_wm[p] = m;
    }
    __syncthreads();

    const int wid  = tid >> 5;
    const int lane = tid & 31;
    const int row  = (blockIdx.x << 3) + wid;
    const int de   = row & (DE - 1);

    // ---- load U row: lane l owns f = l; then grab the two f's this lane needs
    const float u_mine = U[row * 32 + lane];
    const int f_lo = lane >> 1;                 // f for slot-lo (all 4 components)
    const float u_lo = __shfl_sync(0xffffffffu, u_mine, f_lo);
    const float u_hi = __shfl_sync(0xffffffffu, u_mine, f_lo + 16);

    // ---- weights (L1-resident, same (f*8+i) layout as outputs)
    const float4* wa4 = (const float4*)(Wa + de * 256);
    const float4* wt4 = (const float4*)(Wt + de * 256);
    const float4 waL = wa4[lane];
    const float4 waH = wa4[lane + 32];
    const float4 wtL = wt4[lane];
    const float4 wtH = wt4[lane + 32];

    // ---- U_hat_I = u * W_affine
    float4 uiL, uiH;
    uiL.x = u_lo * waL.x; uiL.y = u_lo * waL.y; uiL.z = u_lo * waL.z; uiL.w = u_lo * waL.w;
    uiH.x = u_hi * waH.x; uiH.y = u_hi * waH.y; uiH.z = u_hi * waH.z; uiH.w = u_hi * waH.w;

    float4* oUI = (float4*)(outUI + (size_t)row * 256);
    oUI[lane]      = uiL;
    oUI[lane + 32] = uiH;

    // ---- diag[i] = sum_f ui^2 / 4  (butterfly over same-parity lanes)
    float4 sq;
    sq.x = fmaf(uiL.x, uiL.x, uiH.x * uiH.x);
    sq.y = fmaf(uiL.y, uiL.y, uiH.y * uiH.y);
    sq.z = fmaf(uiL.z, uiL.z, uiH.z * uiH.z);
    sq.w = fmaf(uiL.w, uiL.w, uiH.w * uiH.w);
    #pragma unroll
    for (int m = 2; m <= 16; m <<= 1) {
        sq.x += __shfl_xor_sync(0xffffffffu, sq.x, m);
        sq.y += __shfl_xor_sync(0xffffffffu, sq.y, m);
        sq.z += __shfl_xor_sync(0xffffffffu, sq.z, m);
        sq.w += __shfl_xor_sync(0xffffffffu, sq.w, m);
    }

    // ds = diag * log2e (fold /sqrt(16)); diag >= 0 so row max = ds * maxWt
    const float SC = 0.25f * 1.4426950408889634f;
    float4 ds;
    ds.x = sq.x * SC; ds.y = sq.y * SC; ds.z = sq.z * SC; ds.w = sq.w * SC;

    const float4 mw = *(const float4*)(s_wm + wid * 8 + (lane & 1) * 4);
    float4 mx;
    mx.x = ds.x * mw.x; mx.y = ds.y * mw.y; mx.z = ds.z * mw.z; mx.w = ds.w * mw.w;

    float4 eL, eH;
    eL.x = ex2a(fmaf(ds.x, wtL.x, -mx.x));
    eL.y = ex2a(fmaf(ds.y, wtL.y, -mx.y));
    eL.z = ex2a(fmaf(ds.z, wtL.z, -mx.z));
    eL.w = ex2a(fmaf(ds.w, wtL.w, -mx.w));
    eH.x = ex2a(fmaf(ds.x, wtH.x, -mx.x));
    eH.y = ex2a(fmaf(ds.y, wtH.y, -mx.y));
    eH.z = ex2a(fmaf(ds.z, wtH.z, -mx.z));
    eH.w = ex2a(fmaf(ds.w, wtH.w, -mx.w));

    float4 s;
    s.x = eL.x + eH.x; s.y = eL.y + eH.y; s.z = eL.z + eH.z; s.w = eL.w + eH.w;
    #pragma unroll
    for (int m = 2; m <= 16; m <<= 1) {
        s.x += __shfl_xor_sync(0xffffffffu, s.x, m);
        s.y += __shfl_xor_sync(0xffffffffu, s.y, m);
        s.z += __shfl_xor_sync(0xffffffffu, s.z, m);
        s.w += __shfl_xor_sync(0xffffffffu, s.w, m);
    }

    float4 inv;
    inv.x = rcpa(s.x); inv.y = rcpa(s.y); inv.z = rcpa(s.z); inv.w = rcpa(s.w);

    float4 cL, cH;
    cL.x = eL.x * inv.x; cL.y = eL.y * inv.y; cL.z = eL.z * inv.z; cL.w = eL.w * inv.w;
    cH.x = eH.x * inv.x; cH.y = eH.y * inv.y; cH.z = eH.z * inv.z; cH.w = eH.w * inv.w;

    float4* oC = (float4*)(outC + (size_t)row * 256);
    oC[lane]      = cL;
    oC[lane + 32] = cH;
}

extern "C" void kernel_launch(void* const* d_in, const int* in_sizes, int n_in,
                              void* d_out, int out_size)
{
    const float* U  = (const float*)d_in[0];   // U_hat    (6,422,528)
    const float* Wt = (const float*)d_in[1];   // W_t      (8,192)
    const float* Wa = (const float*)d_in[2];   // W_affine (8,192)
    float* outC  = (float*)d_out;              // C first (return order)
    float* outUI = (float*)d_out + HALF;       // then U_hat_I

    const int blocks = NROWS / 8;              // 25088, one warp per row
    mhsa_main<<<blocks, 256>>>(U, Wt, Wa, outC, outUI);
}

// round 14
// speedup vs baseline: 1.2133x; 1.2133x over previous
#include <cuda_runtime.h>

// Problem constants: B=32, S1=14, S2=14, NC=2, DC=16, F=32, I=8
#define NROWS   200704      // B*S1*S2*NC*DC
#define DE      32          // NC*DC (weights repeat with row period 32)
#define HALF    51380224    // NROWS * F * I (elements per output tensor)

__device__ __forceinline__ float ex2a(float x) {
    float y; asm("ex2.approx.ftz.f32 %0, %1;" : "=f"(y) : "f"(x)); return y;
}
__device__ __forceinline__ float rcpa(float x) {
    float y; asm("rcp.approx.ftz.f32 %0, %1;" : "=f"(y) : "f"(x)); return y;
}

// R2 lane layout: lane owns f_lo = lane>>1 and f_hi = f_lo+16, with the 4
// consecutive i's (lane&1)*4 .. +3 as a float4; all global accesses are fully
// coalesced 512B LDG.128/STG.128.
//
// Speculative-shift softmax: softmax is shift-invariant, so ANY shift in the
// safe window gives correct ratios. Fast path shifts by ds*4 (no reduction,
// no prep kernel). 4.0 ~upper-bounds W_t so no overflow (margin |ds|*1 << 127
// even if max Wt slightly exceeds 4). If the denominator s underflows below
// 2^-60 (heavy-tail ds rows where the deficit ds*(4-maxWt) is huge), the warp
// re-does that row with the EXACT max via a 16-shuffle butterfly — always
// safe, and rare enough to be free on average.
__global__ void __launch_bounds__(256, 8)
mhsa_main(const float* __restrict__ U,
          const float* __restrict__ Wt,
          const float* __restrict__ Wa,
          float* __restrict__ outC,
          float* __restrict__ outUI)
{
    const int warp = (blockIdx.x * blockDim.x + threadIdx.x) >> 5;
    const int lane = threadIdx.x & 31;
    if (warp >= NROWS) return;

    const int row = warp;
    const int de  = row & (DE - 1);

    // ---- load U row: lane l owns f = l; then grab the two f's this lane needs
    const float u_mine = U[row * 32 + lane];
    const int f_lo = lane >> 1;
    const float u_lo = __shfl_sync(0xffffffffu, u_mine, f_lo);
    const float u_hi = __shfl_sync(0xffffffffu, u_mine, f_lo + 16);

    // ---- weights (L1-resident, same (f*8+i) layout as outputs)
    const float4* wa4 = (const float4*)(Wa + de * 256);
    const float4* wt4 = (const float4*)(Wt + de * 256);
    const float4 waL = wa4[lane];
    const float4 waH = wa4[lane + 32];
    const float4 wtL = wt4[lane];
    const float4 wtH = wt4[lane + 32];

    // ---- U_hat_I = u * W_affine
    float4 uiL, uiH;
    uiL.x = u_lo * waL.x; uiL.y = u_lo * waL.y; uiL.z = u_lo * waL.z; uiL.w = u_lo * waL.w;
    uiH.x = u_hi * waH.x; uiH.y = u_hi * waH.y; uiH.z = u_hi * waH.z; uiH.w = u_hi * waH.w;

    float4* oUI = (float4*)(outUI + (size_t)row * 256);
    oUI[lane]      = uiL;
    oUI[lane + 32] = uiH;

    // ---- diag[i] = sum_f ui^2 / 4  (butterfly over same-parity lanes)
    float4 sq;
    sq.x = fmaf(uiL.x, uiL.x, uiH.x * uiH.x);
    sq.y = fmaf(uiL.y, uiL.y, uiH.y * uiH.y);
    sq.z = fmaf(uiL.z, uiL.z, uiH.z * uiH.z);
    sq.w = fmaf(uiL.w, uiL.w, uiH.w * uiH.w);
    #pragma unroll
    for (int m = 2; m <= 16; m <<= 1) {
        sq.x += __shfl_xor_sync(0xffffffffu, sq.x, m);
        sq.y += __shfl_xor_sync(0xffffffffu, sq.y, m);
        sq.z += __shfl_xor_sync(0xffffffffu, sq.z, m);
        sq.w += __shfl_xor_sync(0xffffffffu, sq.w, m);
    }

    const float SC = 0.25f * 1.4426950408889634f;   // fold /sqrt(16) and log2e
    float4 ds;
    ds.x = sq.x * SC; ds.y = sq.y * SC; ds.z = sq.z * SC; ds.w = sq.w * SC;

    // ---- fast path: speculative shift mx = ds * 4
    float4 mx;
    mx.x = ds.x * 4.0f; mx.y = ds.y * 4.0f; mx.z = ds.z * 4.0f; mx.w = ds.w * 4.0f;

    float4 eL, eH;
    eL.x = ex2a(fmaf(ds.x, wtL.x, -mx.x));
    eL.y = ex2a(fmaf(ds.y, wtL.y, -mx.y));
    eL.z = ex2a(fmaf(ds.z, wtL.z, -mx.z));
    eL.w = ex2a(fmaf(ds.w, wtL.w, -mx.w));
    eH.x = ex2a(fmaf(ds.x, wtH.x, -mx.x));
    eH.y = ex2a(fmaf(ds.y, wtH.y, -mx.y));
    eH.z = ex2a(fmaf(ds.z, wtH.z, -mx.z));
    eH.w = ex2a(fmaf(ds.w, wtH.w, -mx.w));

    float4 s;
    s.x = eL.x + eH.x; s.y = eL.y + eH.y; s.z = eL.z + eH.z; s.w = eL.w + eH.w;
    #pragma unroll
    for (int m = 2; m <= 16; m <<= 1) {
        s.x += __shfl_xor_sync(0xffffffffu, s.x, m);
        s.y += __shfl_xor_sync(0xffffffffu, s.y, m);
        s.z += __shfl_xor_sync(0xffffffffu, s.z, m);
        s.w += __shfl_xor_sync(0xffffffffu, s.w, m);
    }

    // ---- underflow check: if any denominator is tiny, redo with exact max
    const float T = 8.6736174e-19f;   // 2^-60
    const float smin = fminf(fminf(s.x, s.y), fminf(s.z, s.w));
    if (__ballot_sync(0xffffffffu, smin < T)) {
        // exact mw[i] = max_f Wt[de,f,i]  (parity butterfly)
        float4 wm;
        wm.x = fmaxf(wtL.x, wtH.x);
        wm.y = fmaxf(wtL.y, wtH.y);
        wm.z = fmaxf(wtL.z, wtH.z);
        wm.w = fmaxf(wtL.w, wtH.w);
        #pragma unroll
        for (int m = 2; m <= 16; m <<= 1) {
            wm.x = fmaxf(wm.x, __shfl_xor_sync(0xffffffffu, wm.x, m));
            wm.y = fmaxf(wm.y, __shfl_xor_sync(0xffffffffu, wm.y, m));
            wm.z = fmaxf(wm.z, __shfl_xor_sync(0xffffffffu, wm.z, m));
            wm.w = fmaxf(wm.w, __shfl_xor_sync(0xffffffffu, wm.w, m));
        }
        mx.x = ds.x * wm.x; mx.y = ds.y * wm.y; mx.z = ds.z * wm.z; mx.w = ds.w * wm.w;

        eL.x = ex2a(fmaf(ds.x, wtL.x, -mx.x));
        eL.y = ex2a(fmaf(ds.y, wtL.y, -mx.y));
        eL.z = ex2a(fmaf(ds.z, wtL.z, -mx.z));
        eL.w = ex2a(fmaf(ds.w, wtL.w, -mx.w));
        eH.x = ex2a(fmaf(ds.x, wtH.x, -mx.x));
        eH.y = ex2a(fmaf(ds.y, wtH.y, -mx.y));
        eH.z = ex2a(fmaf(ds.z, wtH.z, -mx.z));
        eH.w = ex2a(fmaf(ds.w, wtH.w, -mx.w));

        s.x = eL.x + eH.x; s.y = eL.y + eH.y; s.z = eL.z + eH.z; s.w = eL.w + eH.w;
        #pragma unroll
        for (int m = 2; m <= 16; m <<= 1) {
            s.x += __shfl_xor_sync(0xffffffffu, s.x, m);
            s.y += __shfl_xor_sync(0xffffffffu, s.y, m);
            s.z += __shfl_xor_sync(0xffffffffu, s.z, m);
            s.w += __shfl_xor_sync(0xffffffffu, s.w, m);
        }
    }

    float4 inv;
    inv.x = rcpa(s.x); inv.y = rcpa(s.y); inv.z = rcpa(s.z); inv.w = rcpa(s.w);

    float4 cL, cH;
    cL.x = eL.x * inv.x; cL.y = eL.y * inv.y; cL.z = eL.z * inv.z; cL.w = eL.w * inv.w;
    cH.x = eH.x * inv.x; cH.y = eH.y * inv.y; cH.z = eH.z * inv.z; cH.w = eH.w * inv.w;

    float4* oC = (float4*)(outC + (size_t)row * 256);
    oC[lane]      = cL;
    oC[lane + 32] = cH;
}

extern "C" void kernel_launch(void* const* d_in, const int* in_sizes, int n_in,
                              void* d_out, int out_size)
{
    const float* U  = (const float*)d_in[0];   // U_hat    (6,422,528)
    const float* Wt = (const float*)d_in[1];   // W_t      (8,192)
    const float* Wa = (const float*)d_in[2];   // W_affine (8,192)
    float* outC  = (float*)d_out;              // C first (return order)
    float* outUI = (float*)d_out + HALF;       // then U_hat_I

    const int warps_per_block = 8;              // 256 threads
    const int blocks = NROWS / warps_per_block; // 25088
    mhsa_main<<<blocks, 256>>>(U, Wt, Wa, outC, outUI);
}